// round 17
// baseline (speedup 1.0000x reference)
#include <cuda_runtime.h>
#include <cstdint>

#define BB 4
#define TT 2048
#define CC 1024
#define HH 64
#define M0C 10.0f
#define BKT 64

// ---- device scratch (no allocations allowed) ----
__device__ float g_Q[BB * TT * HH];   // 2 MB
__device__ float g_K[BB * TT * HH];   // 2 MB
__device__ float g_V[BB * TT * HH];   // 2 MB
__device__ float g_BS[BB * 32 * HH];  // per-64-row block sums of V (from proj)
__device__ float g_SV[BB * 33 * HH];  // suffix sums of V at 64-aligned starts

// ---- packed f32x2 helpers (sm_100+ FFMA2 path, PTX-only) ----
__device__ __forceinline__ unsigned long long f2_pack2(float x) {
    unsigned long long r;
    unsigned int u = __float_as_uint(x);
    asm("mov.b64 %0, {%1, %1};" : "=l"(r) : "r"(u));
    return r;
}
__device__ __forceinline__ unsigned long long f2_fma(unsigned long long a,
                                                     unsigned long long b,
                                                     unsigned long long c) {
    unsigned long long d;
    asm("fma.rn.f32x2 %0, %1, %2, %3;" : "=l"(d) : "l"(a), "l"(b), "l"(c));
    return d;
}
__device__ __forceinline__ float2 f2_unpack(unsigned long long v) {
    unsigned int lo, hi;
    asm("mov.b64 {%0, %1}, %2;" : "=r"(lo), "=r"(hi) : "l"(v));
    return make_float2(__uint_as_float(lo), __uint_as_float(hi));
}

// cp.async 16B helper (LDGSTS)
__device__ __forceinline__ void cp_async16(void* smem_dst, const void* gmem_src) {
    unsigned int saddr;
    asm("{ .reg .u64 t; cvta.to.shared.u64 t, %1; cvt.u32.u64 %0, t; }"
        : "=r"(saddr) : "l"(smem_dst));
    asm volatile("cp.async.cg.shared.global [%0], [%1], 16;" :: "r"(saddr), "l"(gmem_src));
}
__device__ __forceinline__ void cp_async_commit() {
    asm volatile("cp.async.commit_group;" ::: "memory");
}
__device__ __forceinline__ void cp_async_wait_all() {
    asm volatile("cp.async.wait_group 0;" ::: "memory");
}

// ============================================================
// Kernel 1: projections (R14-proven structure + N-split for occupancy)
// grid (256, 3): bx>>1 = m-tile (BM=64), bx&1 = n-half (BN=32).
// 256 threads: ty=tid>>4 (16 groups x 4 rows), tx=tid&15 (16 x 2 cols).
// Transposed A tile As[16k][68m] (proven conflict-free), Ws[16k][32n].
// FFMA2 m-row pairing: a2 ulonglong2 = 4 rows free; 2 b-packs per kk.
// Register-prefetch software pipeline (one BK=16 step ahead).
// V blocks (mat==2) emit their 32-col partial 64-row sums to g_BS.
// ============================================================
__global__ void __launch_bounds__(256)
proj_kernel(const float* __restrict__ q, const float* __restrict__ k,
            const float* __restrict__ v, const float* __restrict__ Wq,
            const float* __restrict__ Wk, const float* __restrict__ Wv) {
    __shared__ float As[16 * 68];   // transposed A tile [k][m], stride 68
    __shared__ float Ws[16 * 32];   // W tile [k][n-half]

    const int mat = blockIdx.y;
    const float* A = (mat == 0) ? q : (mat == 1) ? k : v;
    const float* W = (mat == 0) ? Wq : (mat == 1) ? Wk : Wv;
    float* O = (mat == 0) ? g_Q : (mat == 1) ? g_K : g_V;

    const int mt = blockIdx.x >> 1;          // 64-row tile index (0..127)
    const int m0 = mt * 64;
    const int n0 = (blockIdx.x & 1) * 32;    // n-half offset
    const int tid = threadIdx.x;
    const int tx = tid & 15, ty = tid >> 4;

    const int arow = tid >> 2, ac4 = tid & 3;   // A loader: 64 rows x 4 float4
    const int wkk = tid >> 3, wc8 = tid & 7;    // W loader (tid<128): 16 k x 8 float4

    const float* Aptr = &A[(size_t)(m0 + arow) * CC + ac4 * 4];
    const float* Wptr = &W[(size_t)wkk * HH + n0 + wc8 * 4];

    unsigned long long acc2[2][2] = {};   // [m-pair][col], packs rows (2ip, 2ip+1)
    float4 av = *(const float4*)Aptr;
    float4 wv = (tid < 128) ? *(const float4*)Wptr : make_float4(0.f, 0.f, 0.f, 0.f);

    for (int k0 = 0; k0 < CC; k0 += 16) {
        __syncthreads();
        As[(ac4 * 4 + 0) * 68 + arow] = av.x;
        As[(ac4 * 4 + 1) * 68 + arow] = av.y;
        As[(ac4 * 4 + 2) * 68 + arow] = av.z;
        As[(ac4 * 4 + 3) * 68 + arow] = av.w;
        if (tid < 128) *(float4*)&Ws[wkk * 32 + wc8 * 4] = wv;
        __syncthreads();
        if (k0 + 16 < CC) {               // prefetch next step (hidden by compute)
            av = *(const float4*)&Aptr[k0 + 16];
            if (tid < 128) wv = *(const float4*)&Wptr[(size_t)(k0 + 16) * HH];
        }
#pragma unroll
        for (int kk = 0; kk < 16; kk++) {
            ulonglong2 a2 = *(const ulonglong2*)&As[kk * 68 + ty * 4];  // rows (0,1),(2,3)
            float2 b2 = *(const float2*)&Ws[kk * 32 + tx * 2];
            unsigned long long bb0 = f2_pack2(b2.x);
            unsigned long long bb1 = f2_pack2(b2.y);
            acc2[0][0] = f2_fma(a2.x, bb0, acc2[0][0]);
            acc2[0][1] = f2_fma(a2.x, bb1, acc2[0][1]);
            acc2[1][0] = f2_fma(a2.y, bb0, acc2[1][0]);
            acc2[1][1] = f2_fma(a2.y, bb1, acc2[1][1]);
        }
    }

    // unpack: acc2[ip][j] -> rows ty*4+2ip+{0,1}, col n0+tx*2+j
    float o[4][2];
#pragma unroll
    for (int ip = 0; ip < 2; ip++)
#pragma unroll
        for (int j = 0; j < 2; j++) {
            float2 t = f2_unpack(acc2[ip][j]);
            o[2 * ip + 0][j] = t.x;
            o[2 * ip + 1][j] = t.y;
        }

#pragma unroll
    for (int i = 0; i < 4; i++) {
        float2 r = make_float2(o[i][0], o[i][1]);
        *(float2*)&O[(size_t)(m0 + ty * 4 + i) * HH + n0 + tx * 2] = r;
    }

    // ---- V blocks: emit 64-row column sums for this 32-col half
    if (mat == 2) {
        float cs0 = o[0][0] + o[1][0] + o[2][0] + o[3][0];
        float cs1 = o[0][1] + o[1][1] + o[2][1] + o[3][1];
        __syncthreads();                    // done reading As
        float* S = As;                      // reuse: [16 ty][32 cols]
        *(float2*)&S[ty * 32 + tx * 2] = make_float2(cs0, cs1);
        __syncthreads();
        if (tid < 32) {
            float s = 0.f;
#pragma unroll
            for (int r = 0; r < 16; r++) s += S[r * 32 + tid];
            g_BS[mt * HH + n0 + tid] = s;
        }
    }
}

// ============================================================
// Kernel 2: suffix sums -> g_SV[b][t] = sum_{j>=64t} V[b][j]
// All 32 loads issued first (MLP=32), one exposed latency.
// ============================================================
__global__ void vsuffix_kernel() {
    const int tid = threadIdx.x;
    const int b = tid >> 6, h = tid & 63;
    float vals[32];
#pragma unroll
    for (int t = 0; t < 32; t++)
        vals[t] = g_BS[(b * 32 + t) * HH + h];
    g_SV[((size_t)b * 33 + 32) * HH + h] = 0.f;
    float acc = 0.f;
#pragma unroll
    for (int t = 31; t >= 0; t--) {
        acc += vals[t];
        g_SV[((size_t)b * 33 + t) * HH + h] = acc;
    }
}

// ============================================================
// Kernel 3: fused causal attention — SINGLE-buffer smem (50.8 KB) for
// 3 blocks/SM (__launch_bounds__(256,3)); cross-block overlap replaces
// double buffering. Staggered prefetch recovers half the overlap free:
// K(kt+1) issued after the Ps-sync (Ks dead), V(kt+1) after the PV-sync.
// 256 blocks complement-paired (same dispatch as R14-proven build).
// Score: 4q x 2k FFMA2 over d-pairs; PV: h-pair FFMA2, parity fold.
// Fixed softmax shift M0; masked tail analytic via g_SV[nkt]; pad=mean(V).
// ============================================================
__global__ void __launch_bounds__(256, 3)
attn_kernel(const int* __restrict__ pad, float* __restrict__ out) {
    extern __shared__ float sm[];
    float* __restrict__ Qs = sm;               // [32][68]  8704 B
    float* __restrict__ Ks = Qs + 32 * 68;     // [64][68] 17408 B
    float* __restrict__ Vs = Ks + 64 * 68;     // [64][64] 16384 B
    float* __restrict__ Ps = Vs + 64 * 64;     // [32][65]  8320 B

    const int bid = blockIdx.x;
    int qt, b;
    if (bid < 108)      { qt = bid >> 2;                b = bid & 3; }
    else if (bid < 148) { qt = 54 + ((bid - 108) >> 2); b = (bid - 108) & 3; }
    else                { qt = 53 - ((bid - 148) >> 2); b = (bid - 148) & 3; }
    const int qb = qt * 32;

    const int tid = threadIdx.x;
    const int tx = tid & 31, ty = tid >> 5;
    const int hg = tx & 15, ks = tx >> 4;
    const int ldr = tid >> 4, ldc4 = tid & 15;
    const float rcpT = 1.0f / (float)TT;
    const float p_rest = __expf(fmaf(1e-9f, 0.125f, -M0C));

    int padf[2];
#pragma unroll
    for (int ii = 0; ii < 2; ii++)
        padf[ii] = pad[b * TT + qb + ty * 4 + ks * 2 + ii];

#pragma unroll
    for (int i2 = 0; i2 < 2; i2++) {
        int idx = tid + i2 * 256;
        int r = idx >> 4, c4 = idx & 15;
        float4 qv = *(const float4*)&g_Q[((size_t)b * TT + qb + r) * HH + c4 * 4];
        *(float4*)&Qs[r * 68 + c4 * 4] = qv;
    }

    unsigned long long o2[4][2] = {};
    float l[4] = {};

    int nkt = (qb + 33 + BKT - 1) >> 6;
    if (nkt > TT / BKT) nkt = TT / BKT;

    // prefetch tile 0 (K and V)
#pragma unroll
    for (int i2 = 0; i2 < 4; i2++) {
        int r = ldr + i2 * 16;
        size_t goff = ((size_t)b * TT + r) * HH + ldc4 * 4;
        cp_async16(&Ks[r * 68 + ldc4 * 4], &g_K[goff]);
        cp_async16(&Vs[r * 64 + ldc4 * 4], &g_V[goff]);
    }
    cp_async_commit();

    for (int kt = 0; kt < nkt; kt++) {
        cp_async_wait_all();
        __syncthreads();            // K(kt), V(kt) visible

        // scores: 4q x 2k per thread (k rows tx, tx+32), FFMA2 over d-pairs
        unsigned long long s2[4][2] = {};
#pragma unroll
        for (int d4 = 0; d4 < 16; d4++) {
            ulonglong2 k2v[2];
#pragma unroll
            for (int j = 0; j < 2; j++)
                k2v[j] = *(const ulonglong2*)&Ks[(tx + 32 * j) * 68 + d4 * 4];
#pragma unroll
            for (int i = 0; i < 4; i++) {
                ulonglong2 a2 = *(const ulonglong2*)&Qs[(ty * 4 + i) * 68 + d4 * 4];
#pragma unroll
                for (int j = 0; j < 2; j++) {
                    s2[i][j] = f2_fma(a2.x, k2v[j].x, s2[i][j]);
                    s2[i][j] = f2_fma(a2.y, k2v[j].y, s2[i][j]);
                }
            }
        }

        // fold pairs, causal mask, exp, stash to Ps
#pragma unroll
        for (int i = 0; i < 4; i++) {
            int qg = qb + ty * 4 + i;
#pragma unroll
            for (int j = 0; j < 2; j++) {
                float2 t = f2_unpack(s2[i][j]);
                float sv = t.x + t.y;
                int kg = kt * BKT + tx + 32 * j;
                sv = (kg <= qg + 1) ? sv : 1e-9f;
                float p = __expf(fmaf(sv, 0.125f, -M0C));
                l[i] += p;
                Ps[(ty * 4 + i) * 65 + tx + 32 * j] = p;
            }
        }
        __syncthreads();            // Ps visible; Ks dead from here

        // prefetch K(kt+1) into Ks while PV runs
        if (kt + 1 < nkt) {
#pragma unroll
            for (int i2 = 0; i2 < 4; i2++) {
                int r = ldr + i2 * 16;
                size_t goff = ((size_t)b * TT + (kt + 1) * BKT + r) * HH + ldc4 * 4;
                cp_async16(&Ks[r * 68 + ldc4 * 4], &g_K[goff]);
            }
            cp_async_commit();
        }

        // PV: lane (hg, ks) accumulates o2[4q][2 h-pairs] over k2 = ks, ks+2, ...
#pragma unroll 8
        for (int k2 = ks; k2 < BKT; k2 += 2) {
            ulonglong2 vv2 = *(const ulonglong2*)&Vs[k2 * 64 + hg * 4];
#pragma unroll
            for (int i = 0; i < 4; i++) {
                unsigned long long p2 = f2_pack2(Ps[(ty * 4 + i) * 65 + k2]);
                o2[i][0] = f2_fma(p2, vv2.x, o2[i][0]);
                o2[i][1] = f2_fma(p2, vv2.y, o2[i][1]);
            }
        }
        __syncthreads();            // PV done reading Vs/Ps

        // prefetch V(kt+1) into Vs
        if (kt + 1 < nkt) {
#pragma unroll
            for (int i2 = 0; i2 < 4; i2++) {
                int r = ldr + i2 * 16;
                size_t goff = ((size_t)b * TT + (kt + 1) * BKT + r) * HH + ldc4 * 4;
                cp_async16(&Vs[r * 64 + ldc4 * 4], &g_V[goff]);
            }
            cp_async_commit();
        }
    }

    float o[4][4];
#pragma unroll
    for (int i = 0; i < 4; i++) {
        float2 t0 = f2_unpack(o2[i][0]);
        float2 t1 = f2_unpack(o2[i][1]);
        o[i][0] = t0.x; o[i][1] = t0.y; o[i][2] = t1.x; o[i][3] = t1.y;
    }

#pragma unroll
    for (int i = 0; i < 4; i++)
#pragma unroll
        for (int c = 0; c < 4; c++)
            o[i][c] += __shfl_xor_sync(0xffffffffu, o[i][c], 16);

    float linv[4];
    const int KE = nkt * BKT;
    const float n_rest = (float)(TT - KE);
#pragma unroll
    for (int i = 0; i < 4; i++) {
        float li = l[i];
#pragma unroll
        for (int off = 1; off < 32; off <<= 1)
            li += __shfl_xor_sync(0xffffffffu, li, off);
        linv[i] = 1.0f / (li + n_rest * p_rest);
    }

    float4 sv4 = *(const float4*)&g_SV[((size_t)b * 33 + nkt) * HH + hg * 4];
    float4 mv4 = *(const float4*)&g_SV[((size_t)b * 33 + 0) * HH + hg * 4];

#pragma unroll
    for (int ii = 0; ii < 2; ii++) {
        int i = ks * 2 + ii;
        int qg = qb + ty * 4 + i;
        float4 r;
        if (padf[ii] == 1) {
            r = make_float4(mv4.x * rcpT, mv4.y * rcpT, mv4.z * rcpT, mv4.w * rcpT);
        } else {
            r.x = fmaf(p_rest, sv4.x, o[i][0]) * linv[i];
            r.y = fmaf(p_rest, sv4.y, o[i][1]) * linv[i];
            r.z = fmaf(p_rest, sv4.z, o[i][2]) * linv[i];
            r.w = fmaf(p_rest, sv4.w, o[i][3]) * linv[i];
        }
        *(float4*)&out[((size_t)b * TT + qg) * HH + hg * 4] = r;
    }
}

// ============================================================
extern "C" void kernel_launch(void* const* d_in, const int* in_sizes, int n_in,
                              void* d_out, int out_size) {
    const float* q  = (const float*)d_in[0];
    const float* k  = (const float*)d_in[1];
    const float* v  = (const float*)d_in[2];
    const float* Wq = (const float*)d_in[3];
    const float* Wk = (const float*)d_in[4];
    const float* Wv = (const float*)d_in[5];
    const int* pad  = (const int*)d_in[6];
    float* out = (float*)d_out;

    const int attn_smem =
        (32 * 68 + 64 * 68 + 64 * 64 + 32 * 65) * 4;  // 50816 B
    cudaFuncSetAttribute(attn_kernel, cudaFuncAttributeMaxDynamicSharedMemorySize, attn_smem);

    proj_kernel<<<dim3(256, 3), 256>>>(q, k, v, Wq, Wk, Wv);
    vsuffix_kernel<<<1, 256>>>();
    attn_kernel<<<256, 256, attn_smem>>>(pad, out);
}